// round 11
// baseline (speedup 1.0000x reference)
#include <cuda_runtime.h>

#define BB 64      // batch
#define SS 512     // sequence length
#define EE 256     // embedding dim
#define HH 512     // hidden

typedef unsigned long long u64;
typedef unsigned int u32;

// ---------------------------------------------------------------------------
// Device globals
// ---------------------------------------------------------------------------
__device__ u32 g_wf[128];                     // per-CTA h write-flags (monotonic)
__device__ float g_h[4][HH * BB];             // h ring: slot s&3 = h(s), [k][b]

// ---------------------------------------------------------------------------
// f32x2 helpers (packed FFMA2/FADD2 -- only reachable via PTX)
// ---------------------------------------------------------------------------
__device__ __forceinline__ u64 fma2(u64 a, u64 b, u64 c) {
    u64 d; asm("fma.rn.f32x2 %0, %1, %2, %3;" : "=l"(d) : "l"(a), "l"(b), "l"(c)); return d;
}
__device__ __forceinline__ u64 add2(u64 a, u64 b) {
    u64 d; asm("add.rn.f32x2 %0, %1, %2;" : "=l"(d) : "l"(a), "l"(b)); return d;
}
__device__ __forceinline__ u64 pack2(float x, float y) {
    u64 d; asm("mov.b64 %0, {%1, %2};" : "=l"(d) : "f"(x), "f"(y)); return d;
}
__device__ __forceinline__ float2 unpack2(u64 v) {
    float2 r; asm("mov.b64 {%0, %1}, %2;" : "=f"(r.x), "=f"(r.y) : "l"(v)); return r;
}
__device__ __forceinline__ float sigf(float x) { return 1.f / (1.f + __expf(-x)); }
__device__ __forceinline__ float tanh_f(float x) { return 2.f / (1.f + __expf(-2.f * x)) - 1.f; }

// SMEM layout (float offsets)
#define OFF_WHH  0        // 8192 floats : W_hh pairs {w_jA,w_jB}        (32KB)
#define OFF_WIH  8192     // 4096 floats : W_ih pairs {w_jA,w_jB}        (16KB)
#define OFF_SCP  12288    // 8192 floats : reduce scratch [st8][kr8][b64](32KB)
#define OFF_BIAS 20480    // 16 floats   : bias pairs per stream
#define OFF_MISC 20496    // 2           : [0]=is64 [1]=flag base
#define SMEM_FLOATS 20512

// ---------------------------------------------------------------------------
// Fused persistent LSTM: 128 CTAs x 256 threads (8 warps), single launch.
// CTA owns 4 h-columns j0..j0+3 (8 f32x2 streams st = g*2+jp, vector=j-pair).
// Per step, gates = W_ih.emb(s) + W_hh.h(s-1) + bias as ONE augmented dot:
//   1) emb part: warp wi owns E-range [wi*32,+32); emb rows for the lane's
//      b-pair stream straight from L2 into registers (no staging); computed
//      BEFORE polling -> fills the producer-tail wait window. Bias in warp 0's
//      accumulator init.
//   2) h part: identical to R10 (b-pair LDG.64, 8-k chunks, prefetch dist 3,
//      one acquire-poll per warp over its 16 producer flags).
// Ring depth 4 + all-warps-cover-all-flags => slot reuse safe; flags
// monotonic => graph-replay safe. No grid barrier, no g_xg, one launch.
// ---------------------------------------------------------------------------
__global__ void __launch_bounds__(256, 1) lstm_kernel(
    const void* __restrict__ seq, const float* __restrict__ emb,
    const float* __restrict__ Wih, const float* __restrict__ Whh,
    const float* __restrict__ bih, const float* __restrict__ bhh,
    float* __restrict__ out, int write_c)
{
    extern __shared__ float smf[];
    float*  Ws  = smf + OFF_WHH;            // (st*512+k)*2
    float*  Wi  = smf + OFF_WIH;            // (st*256+k)*2
    float2* scp = (float2*)(smf + OFF_SCP); // [st8][kr8][b64]
    u32* miscp  = (u32*)(smf + OFF_MISC);

    const int tid  = threadIdx.x;
    const int wi   = tid >> 5;
    const int lane = tid & 31;
    const int cta  = blockIdx.x;
    const int j0   = cta * 4;
    const int kbase = wi * 64;      // h k-range
    const int ebase = wi * 32;      // emb E-range

    if (tid == 0) { miscp[0] = 1u; miscp[1] = g_wf[cta]; }
    __syncthreads();
    if (tid < 64) {
        if (((const u32*)seq)[2 * tid + 1] != 0u) miscp[0] = 0u;
    }

    // W_hh pairs: st = g*2+jp covers rows (g*H + j0+2jp, +1), K=512
    #pragma unroll
    for (int st = 0; st < 8; st++) {
        int g = st >> 1, jp = st & 1;
        const float* r0 = Whh + (size_t)(g * HH + j0 + 2 * jp) * HH;
        const float* r1 = r0 + HH;
        #pragma unroll
        for (int i = 0; i < 2; i++) {
            int k = tid + i * 256;
            *(float2*)&Ws[(st * 512 + k) * 2] = make_float2(r0[k], r1[k]);
        }
    }
    // W_ih pairs: same row structure, K=256
    #pragma unroll
    for (int st = 0; st < 8; st++) {
        int g = st >> 1, jp = st & 1;
        int rowA = g * HH + j0 + 2 * jp;
        *(float2*)&Wi[(st * 256 + tid) * 2] =
            make_float2(Wih[(size_t)rowA * EE + tid],
                        Wih[(size_t)(rowA + 1) * EE + tid]);
    }
    // bias pairs
    if (tid < 8) {
        int g = tid >> 1, jp = tid & 1;
        int rowA = g * HH + j0 + 2 * jp;
        *(float2*)&smf[OFF_BIAS + tid * 2] =
            make_float2(bih[rowA] + bhh[rowA], bih[rowA + 1] + bhh[rowA + 1]);
    }
    __syncthreads();

    const int b  = tid & 63;        // epilogue: one (b, j) per thread
    const int jj = tid >> 6;
    const int j  = j0 + jj;
    const int jp_r = jj >> 1;
    const int comp = jj & 1;
    const u32 base = miscp[1];
    const int is64 = (int)miscp[0];

    const int bA = 2 * lane, bN = 2 * lane + 1;   // lane's b-pair

    float c_reg = 0.f, h_val = 0.f;

    #pragma unroll 1
    for (int s = 0; s < SS; s++) {
        // ---- seq indices for this lane's b-pair ----
        int r0i, r1i;
        if (is64) {
            r0i = (int)((const long long*)seq)[bA * SS + s];
            r1i = (int)((const long long*)seq)[bN * SS + s];
        } else {
            r0i = ((const int*)seq)[bA * SS + s];
            r1i = ((const int*)seq)[bN * SS + s];
        }

        // ---- emb rows into registers (16 LDG.128, high MLP) ----
        float4 ea[8], eb[8];
        {
            const float* e0 = emb + (size_t)r0i * EE + ebase;
            const float* e1 = emb + (size_t)r1i * EE + ebase;
            #pragma unroll
            for (int i = 0; i < 8; i++) {
                ea[i] = *(const float4*)(e0 + i * 4);
                eb[i] = *(const float4*)(e1 + i * 4);
            }
        }

        // ---- acc init: bias (warp 0 only, so it sums once in the reduce) ----
        u64 acc[8][2];
        #pragma unroll
        for (int st = 0; st < 8; st++) {
            u64 bv = (wi == 0) ? *(const u64*)&smf[OFF_BIAS + st * 2] : 0ull;
            acc[st][0] = bv; acc[st][1] = bv;
        }

        // ---- emb part: K=256 split 32/warp (overlaps producer tails) ----
        #pragma unroll
        for (int i = 0; i < 8; i++) {
            #pragma unroll
            for (int half = 0; half < 2; half++) {
                const int kE = ebase + i * 4 + half * 2;
                float ax = half ? ea[i].z : ea[i].x;
                float ay = half ? ea[i].w : ea[i].y;
                float bx = half ? eb[i].z : eb[i].x;
                float by = half ? eb[i].w : eb[i].y;
                u64 dA0 = pack2(ax, ax), dB0 = pack2(bx, bx);
                u64 dA1 = pack2(ay, ay), dB1 = pack2(by, by);
                #pragma unroll
                for (int st = 0; st < 8; st++) {
                    ulonglong2 wv = *(const ulonglong2*)&Wi[(st * 256 + kE) * 2];
                    acc[st][0] = fma2(dA0, wv.x, acc[st][0]);
                    acc[st][1] = fma2(dB0, wv.x, acc[st][1]);
                    acc[st][0] = fma2(dA1, wv.y, acc[st][0]);
                    acc[st][1] = fma2(dB1, wv.y, acc[st][1]);
                }
            }
        }

        // ---- h part (s > 0): wait, then K=512 GEMM as in R10 ----
        if (s > 0) {
            const u32 target = base + (u32)s;
            int ok, first = 1;
            do {
                if (!first) __nanosleep(20);
                first = 0;
                ok = 1;
                if (lane < 16) {
                    u32 f;
                    asm volatile("ld.acquire.gpu.global.u32 %0, [%1];"
                                 : "=r"(f) : "l"(&g_wf[wi * 16 + lane]));
                    ok = ((int)(f - target) >= 0);
                }
            } while (__all_sync(0xffffffffu, ok) == 0);

            const float2* hsrc = (const float2*)g_h[(s - 1) & 3];  // [k][b/2]
            float2 hreg[4][8];
            #pragma unroll
            for (int c = 0; c < 3; c++)
                #pragma unroll
                for (int i = 0; i < 8; i++)
                    hreg[c][i] = __ldcg(&hsrc[(kbase + c * 8 + i) * 32 + lane]);

            #pragma unroll
            for (int c = 0; c < 8; c++) {
                const int cur = c & 3;
                if (c < 5) {
                    const int pb = (c + 3) & 3;
                    const int kn = kbase + (c + 3) * 8;
                    #pragma unroll
                    for (int i = 0; i < 8; i++)
                        hreg[pb][i] = __ldcg(&hsrc[(kn + i) * 32 + lane]);
                }
                const int kg0 = kbase + c * 8;
                #pragma unroll
                for (int kk = 0; kk < 8; kk += 2) {
                    const int kg = kg0 + kk;
                    float2 v0 = hreg[cur][kk];
                    float2 v1 = hreg[cur][kk + 1];
                    u64 dA0 = pack2(v0.x, v0.x);
                    u64 dB0 = pack2(v0.y, v0.y);
                    u64 dA1 = pack2(v1.x, v1.x);
                    u64 dB1 = pack2(v1.y, v1.y);
                    #pragma unroll
                    for (int st = 0; st < 8; st++) {
                        ulonglong2 wv = *(const ulonglong2*)&Ws[(st * 512 + kg) * 2];
                        acc[st][0] = fma2(dA0, wv.x, acc[st][0]);
                        acc[st][1] = fma2(dB0, wv.x, acc[st][1]);
                        acc[st][0] = fma2(dA1, wv.y, acc[st][0]);
                        acc[st][1] = fma2(dB1, wv.y, acc[st][1]);
                    }
                }
            }
        }

        // ---- partials -> scratch [st][kr][b], one STS.128 per stream ----
        #pragma unroll
        for (int st = 0; st < 8; st++) {
            float2 p0 = *(float2*)&acc[st][0];
            float2 p1 = *(float2*)&acc[st][1];
            *(float4*)&scp[(st * 8 + wi) * 64 + 2 * lane] =
                make_float4(p0.x, p0.y, p1.x, p1.y);
        }
        __syncthreads();

        // ---- cross-warp reduce (packed f32x2) + gates ----
        float gt[4];
        #pragma unroll
        for (int g = 0; g < 4; g++) {
            int st = g * 2 + jp_r;
            const u64* rb = (const u64*)&scp[(st * 8) * 64 + b];
            u64 v0 = add2(rb[0 * 64], rb[1 * 64]);
            u64 v1 = add2(rb[2 * 64], rb[3 * 64]);
            u64 v2 = add2(rb[4 * 64], rb[5 * 64]);
            u64 v3 = add2(rb[6 * 64], rb[7 * 64]);
            float2 r = unpack2(add2(add2(v0, v1), add2(v2, v3)));
            gt[g] = comp ? r.y : r.x;
        }
        float ig = sigf(gt[0]), fg = sigf(gt[1]);
        float gg = tanh_f(gt[2]), og = sigf(gt[3]);
        c_reg = fg * c_reg + ig * gg;
        h_val = og * tanh_f(c_reg);

        __stcg(&g_h[s & 3][j * 64 + b], h_val);
        __syncthreads();   // all h stores of this CTA issued before flag bump
        if (tid == 0) {
            asm volatile("red.release.gpu.global.add.u32 [%0], %1;"
                         :: "l"(&g_wf[cta]), "r"(1u) : "memory");
        }
    }

    out[b * HH + j] = h_val;
    if (write_c) out[BB * HH + b * HH + j] = c_reg;
}

// ---------------------------------------------------------------------------
// kernel_launch: single fused launch
// ---------------------------------------------------------------------------
extern "C" void kernel_launch(void* const* d_in, const int* in_sizes, int n_in,
                              void* d_out, int out_size)
{
    const void*  seq = d_in[0];
    const float* emb = (const float*)d_in[1];
    const float* Wih = (const float*)d_in[2];
    const float* Whh = (const float*)d_in[3];
    const float* bih = (const float*)d_in[4];
    const float* bhh = (const float*)d_in[5];
    float* out = (float*)d_out;

    (void)in_sizes; (void)n_in;
    int write_c = (out_size >= 2 * BB * HH) ? 1 : 0;

    static const int kSmem = SMEM_FLOATS * (int)sizeof(float);   // ~80.1 KB
    cudaFuncSetAttribute(lstm_kernel, cudaFuncAttributeMaxDynamicSharedMemorySize, kSmem);

    lstm_kernel<<<HH / 4, 256, kSmem>>>(seq, emb, Wih, Whh, bih, bhh, out, write_c);
}